// round 1
// baseline (speedup 1.0000x reference)
#include <cuda_runtime.h>
#include <cuda_bf16.h>

#define N_NODES 200000
#define N_EDGES 6400000
#define ATTD 16

// Per-node accumulator: {sum_exp, sum_exp*vx, sum_exp*vy, pad}
__device__ float4 g_acc[N_NODES];

__global__ void init_kernel(int n) {
    int i = blockIdx.x * blockDim.x + threadIdx.x;
    if (i < n) g_acc[i] = make_float4(0.f, 0.f, 0.f, 0.f);
}

__global__ void edge_kernel(const float2* __restrict__ x,
                            const int* __restrict__ row_idx,
                            const int* __restrict__ col_idx,
                            const float* __restrict__ W1,
                            const float* __restrict__ b1,
                            const float* __restrict__ W2,
                            int E) {
    // Load tiny MLP weights once per thread (amortized over grid-stride loop)
    float w1x[ATTD], w1y[ATTD], bb1[ATTD], w2[ATTD];
#pragma unroll
    for (int k = 0; k < ATTD; k++) {
        w1x[k] = __ldg(W1 + k);
        w1y[k] = __ldg(W1 + ATTD + k);
        bb1[k] = __ldg(b1 + k);
        w2[k]  = __ldg(W2 + k);
    }

    for (int e = blockIdx.x * blockDim.x + threadIdx.x; e < E;
         e += gridDim.x * blockDim.x) {
        int r = __ldg(row_idx + e);
        int c = __ldg(col_idx + e);
        float2 xi = __ldg(x + r);
        float2 xj = __ldg(x + c);

        // u = mobius_add(-xi, xj, c=1)
        float ax = -xi.x, ay = -xi.y;
        float ab = ax * xj.x + ay * xj.y;
        float aa = xi.x * xi.x + xi.y * xi.y;   // |a|^2 = |xi|^2
        float bb = xj.x * xj.x + xj.y * xj.y;
        float na = 1.f + 2.f * ab + bb;
        float nb = 1.f - aa;
        float den = fmaxf(1.f + 2.f * ab + aa * bb, 1e-15f);
        float inv_den = __frcp_rn(den);
        float ux = (na * ax + nb * xj.x) * inv_den;
        float uy = (na * ay + nb * xj.y) * inv_den;

        // v = log_{xi}(xj):  (1-|xi|^2) * atanh(min(|u|, 1-1e-5)) * u/|u|
        float un2 = fmaxf(ux * ux + uy * uy, 1e-30f);
        float inv_un = rsqrtf(un2);
        float un = un2 * inv_un;                // = max(|u|, 1e-15)
        float z = fminf(un, 1.f - 1e-5f);
        float at = 0.5f * __logf((1.f + z) * __frcp_rn(1.f - z));  // atanh(z)
        float factor = fmaxf(nb, 1e-15f) * at * inv_un;
        float vx = factor * ux;
        float vy = factor * uy;

        // score = gelu_exact(v@W1 + b1) @ W2
        float s = 0.f;
#pragma unroll
        for (int k = 0; k < ATTD; k++) {
            float pre = fmaf(vx, w1x[k], fmaf(vy, w1y[k], bb1[k]));
            float g = 0.5f * pre * (1.f + erff(pre * 0.70710678118654752f));
            s = fmaf(g, w2[k], s);
        }

        // softmax without max-subtraction (scores are bounded, no overflow)
        float ex = __expf(s);

        // single vectorized reduction: {sum_exp, sum_exp*vx, sum_exp*vy, 0}
        float4* dst = &g_acc[r];
        asm volatile("red.global.add.v4.f32 [%0], {%1, %2, %3, %4};"
                     :: "l"(dst), "f"(ex), "f"(ex * vx), "f"(ex * vy), "f"(0.f)
                     : "memory");
    }
}

__global__ void node_kernel(const float2* __restrict__ x,
                            const int* __restrict__ depth,
                            const float* __restrict__ eta_p,
                            const float* __restrict__ depth_scale,
                            const float* __restrict__ depth_theta,
                            float2* __restrict__ out,
                            int n) {
    int i = blockIdx.x * blockDim.x + threadIdx.x;
    if (i >= n) return;

    float4 acc = g_acc[i];
    float inv_d = __frcp_rn(fmaxf(acc.x, 1e-15f));
    float mx = acc.y * inv_d;
    float my = acc.z * inv_d;

    // depth-gated rotation/scale
    int d = min(max(__ldg(depth + i), 0), 511);
    float k = __ldg(depth_scale + d);
    float ang = __ldg(depth_theta + d);
    float sa, ca;
    sincosf(ang, &sa, &ca);
    float tx = k * (ca * mx - sa * my);
    float ty = k * (sa * mx + ca * my);

    // exp_x(eta * m)
    float eta = __ldg(eta_p);
    float wx = eta * tx;
    float wy = eta * ty;
    float wn2 = fmaxf(wx * wx + wy * wy, 1e-30f);
    float inv_wn = rsqrtf(wn2);
    float wn = wn2 * inv_wn;                   // = max(|w|, 1e-15)
    float2 xx = __ldg(x + i);
    float aa = xx.x * xx.x + xx.y * xx.y;
    float lam = 2.f * __frcp_rn(fmaxf(1.f - aa, 1e-15f));
    float th = tanhf(0.5f * lam * wn);
    float sx = th * wx * inv_wn;
    float sy = th * wy * inv_wn;

    // mobius_add(x, second)
    float ab = xx.x * sx + xx.y * sy;
    float bb = sx * sx + sy * sy;
    float na = 1.f + 2.f * ab + bb;
    float nb = 1.f - aa;
    float den = fmaxf(1.f + 2.f * ab + aa * bb, 1e-15f);
    float inv_den = __frcp_rn(den);
    out[i] = make_float2((na * xx.x + nb * sx) * inv_den,
                         (na * xx.y + nb * sy) * inv_den);
}

extern "C" void kernel_launch(void* const* d_in, const int* in_sizes, int n_in,
                              void* d_out, int out_size) {
    const float2* x  = (const float2*)d_in[0];
    const int* ei    = (const int*)d_in[1];
    const int* depth = (const int*)d_in[2];
    const float* W1  = (const float*)d_in[3];
    const float* b1  = (const float*)d_in[4];
    const float* W2  = (const float*)d_in[5];
    const float* eta = (const float*)d_in[6];
    const float* dsc = (const float*)d_in[7];
    const float* dth = (const float*)d_in[8];
    float2* out = (float2*)d_out;

    int N = in_sizes[0] / 2;
    int E = in_sizes[1] / 2;

    init_kernel<<<(N + 255) / 256, 256>>>(N);
    edge_kernel<<<592, 256>>>(x, ei, ei + E, W1, b1, W2, E);
    node_kernel<<<(N + 255) / 256, 256>>>(x, depth, eta, dsc, dth, out, N);
}

// round 5
// speedup vs baseline: 1.5808x; 1.5808x over previous
#include <cuda_runtime.h>
#include <cuda_bf16.h>

#define N_NODES 200000
#define ATTD 16

// Per-node accumulator: {sum_exp, sum_exp*vx, sum_exp*vy, pad}
__device__ float4 g_acc[N_NODES];

// ---------- packed f32x2 helpers ----------
typedef unsigned long long f2;

__device__ __forceinline__ f2 pk(float a, float b) {
    f2 r; asm("mov.b64 %0, {%1, %2};" : "=l"(r) : "f"(a), "f"(b)); return r;
}
__device__ __forceinline__ void upk(f2 v, float& a, float& b) {
    asm("mov.b64 {%0, %1}, %2;" : "=f"(a), "=f"(b) : "l"(v));
}
__device__ __forceinline__ f2 fma2(f2 a, f2 b, f2 c) {
    f2 r; asm("fma.rn.f32x2 %0, %1, %2, %3;" : "=l"(r) : "l"(a), "l"(b), "l"(c)); return r;
}
__device__ __forceinline__ f2 mul2(f2 a, f2 b) {
    f2 r; asm("mul.rn.f32x2 %0, %1, %2;" : "=l"(r) : "l"(a), "l"(b)); return r;
}
__device__ __forceinline__ f2 add2(f2 a, f2 b) {
    f2 r; asm("add.rn.f32x2 %0, %1, %2;" : "=l"(r) : "l"(a), "l"(b)); return r;
}
__device__ __forceinline__ float tanh_ap(float x) {
    float y; asm("tanh.approx.f32 %0, %1;" : "=f"(y) : "f"(x)); return y;
}
__device__ __forceinline__ float rcp_ap(float x) {
    float y; asm("rcp.approx.f32 %0, %1;" : "=f"(y) : "f"(x)); return y;
}
__device__ __forceinline__ float rsqrt_ap(float x) {
    float y; asm("rsqrt.approx.f32 %0, %1;" : "=f"(y) : "f"(x)); return y;
}

__global__ void init_kernel(int n) {
    int i = blockIdx.x * blockDim.x + threadIdx.x;
    if (i < n) g_acc[i] = make_float4(0.f, 0.f, 0.f, 0.f);
}

__global__ void edge_kernel(const float2* __restrict__ x,
                            const int2* __restrict__ row2,
                            const int2* __restrict__ col2,
                            const float* __restrict__ W1,
                            const float* __restrict__ b1,
                            const float* __restrict__ W2,
                            int E) {
    // Broadcast-packed weights in shared memory (LDS.64 broadcast, conflict-free)
    __shared__ f2 sw1x[ATTD], sw1y[ATTD], sb1[ATTD], shw2[ATTD];
    if (threadIdx.x < ATTD) {
        int k = threadIdx.x;
        float a = __ldg(W1 + k);
        float b = __ldg(W1 + ATTD + k);
        float c = __ldg(b1 + k);
        float d = 0.5f * __ldg(W2 + k);
        sw1x[k] = pk(a, a);
        sw1y[k] = pk(b, b);
        sb1[k]  = pk(c, c);
        shw2[k] = pk(d, d);
    }
    __syncthreads();

    const f2 ONE  = pk(1.f, 1.f);
    const f2 NEG1 = pk(-1.f, -1.f);
    const f2 TWO  = pk(2.f, 2.f);
    const f2 G0   = pk(0.7978845608028654f, 0.7978845608028654f);
    const f2 G1   = pk(0.0356774081363f, 0.0356774081363f);  // 0.7978845608*0.044715

    int npairs = (E + 1) >> 1;
    for (int i = blockIdx.x * blockDim.x + threadIdx.x; i < npairs;
         i += gridDim.x * blockDim.x) {
        int2 rr = __ldg(row2 + i);
        int2 cc = __ldg(col2 + i);
        bool has2 = (2 * i + 1 < E);
        if (!has2) { rr.y = rr.x; cc.y = cc.x; }  // duplicate, skip 2nd red

        float2 xi0 = __ldg(x + rr.x);
        float2 xi1 = __ldg(x + rr.y);
        float2 xj0 = __ldg(x + cc.x);
        float2 xj1 = __ldg(x + cc.y);

        // a = -xi (negated at pack time)
        f2 AX  = pk(-xi0.x, -xi1.x);
        f2 AY  = pk(-xi0.y, -xi1.y);
        f2 XJX = pk(xj0.x, xj1.x);
        f2 XJY = pk(xj0.y, xj1.y);

        // mobius_add(a, xj), c=1.  dn = dot(a,xj)
        f2 DN = fma2(AY, XJY, mul2(AX, XJX));
        f2 AA = fma2(AY, AY, mul2(AX, AX));
        f2 BB = fma2(XJY, XJY, mul2(XJX, XJX));
        f2 NA = fma2(TWO, DN, add2(BB, ONE));       // 1 + 2 a.b + |b|^2
        f2 NB = fma2(AA, NEG1, ONE);                // 1 - |a|^2  (>0.75, no clamp)
        f2 DEN = fma2(TWO, DN, fma2(AA, BB, ONE));  // >0.5 always, no clamp

        float d0, d1;
        upk(DEN, d0, d1);
        f2 IDEN = pk(rcp_ap(d0), rcp_ap(d1));

        f2 UX = mul2(fma2(NA, AX, mul2(NB, XJX)), IDEN);
        f2 UY = mul2(fma2(NA, AY, mul2(NB, XJY)), IDEN);

        // v = (1-|xi|^2) * atanh(min(|u|,1-1e-5)) * u/|u|
        f2 UN2 = fma2(UY, UY, mul2(UX, UX));
        float un20, un21;
        upk(UN2, un20, un21);
        un20 = fmaxf(un20, 1e-30f);
        un21 = fmaxf(un21, 1e-30f);
        float ir0 = rsqrt_ap(un20), ir1 = rsqrt_ap(un21);
        float z0 = fminf(un20 * ir0, 1.f - 1e-5f);
        float z1 = fminf(un21 * ir1, 1.f - 1e-5f);
        // atanh(z) = 0.5*log((1+z)/(1-z))
        float at0 = 0.5f * __logf((1.f + z0) * rcp_ap(1.f - z0));
        float at1 = 0.5f * __logf((1.f + z1) * rcp_ap(1.f - z1));

        f2 FACT = mul2(mul2(NB, pk(at0, at1)), pk(ir0, ir1));
        f2 VX = mul2(FACT, UX);
        f2 VY = mul2(FACT, UY);

        // tiny MLP with tanh-form GELU (MUFU.TANH)
        f2 S = pk(0.f, 0.f);
#pragma unroll
        for (int k = 0; k < ATTD; k++) {
            f2 PRE = fma2(VX, sw1x[k], fma2(VY, sw1y[k], sb1[k]));
            f2 P2 = mul2(PRE, PRE);
            f2 ARG = mul2(fma2(P2, G1, G0), PRE);
            float a0, a1;
            upk(ARG, a0, a1);
            f2 TH = pk(tanh_ap(a0), tanh_ap(a1));
            f2 T = mul2(PRE, shw2[k]);
            S = add2(S, T);
            S = fma2(T, TH, S);
        }

        float s0, s1;
        upk(S, s0, s1);
        float vx0, vx1, vy0, vy1;
        upk(VX, vx0, vx1);
        upk(VY, vy0, vy1);

        float ex0 = __expf(s0);
        float4* dst0 = &g_acc[rr.x];
        asm volatile("red.global.add.v4.f32 [%0], {%1, %2, %3, %4};"
                     :: "l"(dst0), "f"(ex0), "f"(ex0 * vx0), "f"(ex0 * vy0), "f"(0.f)
                     : "memory");
        if (has2) {
            float ex1 = __expf(s1);
            float4* dst1 = &g_acc[rr.y];
            asm volatile("red.global.add.v4.f32 [%0], {%1, %2, %3, %4};"
                         :: "l"(dst1), "f"(ex1), "f"(ex1 * vx1), "f"(ex1 * vy1), "f"(0.f)
                         : "memory");
        }
    }
}

__global__ void node_kernel(const float2* __restrict__ x,
                            const int* __restrict__ depth,
                            const float* __restrict__ eta_p,
                            const float* __restrict__ depth_scale,
                            const float* __restrict__ depth_theta,
                            float2* __restrict__ out,
                            int n) {
    int i = blockIdx.x * blockDim.x + threadIdx.x;
    if (i >= n) return;

    float4 acc = g_acc[i];
    float inv_d = __frcp_rn(fmaxf(acc.x, 1e-15f));
    float mx = acc.y * inv_d;
    float my = acc.z * inv_d;

    int d = min(max(__ldg(depth + i), 0), 511);
    float k = __ldg(depth_scale + d);
    float ang = __ldg(depth_theta + d);
    float sa, ca;
    sincosf(ang, &sa, &ca);
    float tx = k * (ca * mx - sa * my);
    float ty = k * (sa * mx + ca * my);

    float eta = __ldg(eta_p);
    float wx = eta * tx;
    float wy = eta * ty;
    float wn2 = fmaxf(wx * wx + wy * wy, 1e-30f);
    float inv_wn = rsqrtf(wn2);
    float wn = wn2 * inv_wn;
    float2 xx = __ldg(x + i);
    float aa = xx.x * xx.x + xx.y * xx.y;
    float lam = 2.f * __frcp_rn(fmaxf(1.f - aa, 1e-15f));
    float th = tanhf(0.5f * lam * wn);
    float sx = th * wx * inv_wn;
    float sy = th * wy * inv_wn;

    float ab = xx.x * sx + xx.y * sy;
    float bb = sx * sx + sy * sy;
    float na = 1.f + 2.f * ab + bb;
    float nb = 1.f - aa;
    float den = fmaxf(1.f + 2.f * ab + aa * bb, 1e-15f);
    float inv_den = __frcp_rn(den);
    out[i] = make_float2((na * xx.x + nb * sx) * inv_den,
                         (na * xx.y + nb * sy) * inv_den);
}

extern "C" void kernel_launch(void* const* d_in, const int* in_sizes, int n_in,
                              void* d_out, int out_size) {
    const float2* x  = (const float2*)d_in[0];
    const int* ei    = (const int*)d_in[1];
    const int* depth = (const int*)d_in[2];
    const float* W1  = (const float*)d_in[3];
    const float* b1  = (const float*)d_in[4];
    const float* W2  = (const float*)d_in[5];
    const float* eta = (const float*)d_in[6];
    const float* dsc = (const float*)d_in[7];
    const float* dth = (const float*)d_in[8];
    float2* out = (float2*)d_out;

    int N = in_sizes[0] / 2;
    int E = in_sizes[1] / 2;

    init_kernel<<<(N + 255) / 256, 256>>>(N);
    edge_kernel<<<2048, 128>>>(x, (const int2*)ei, (const int2*)(ei + E),
                               W1, b1, W2, E);
    node_kernel<<<(N + 255) / 256, 256>>>(x, depth, eta, dsc, dth, out, N);
}